// round 3
// baseline (speedup 1.0000x reference)
#include <cuda_runtime.h>
#include <math.h>

// Problem constants
#define B_DIM 64
#define S_DIM 4096
#define C_DIM 128
#define N2 2048          // half-length complex FFT size
#define NTHREADS 256
#define TOPK 64

// 128 MB scratch in (B, C, S) layout
__device__ float g_scratch[(size_t)B_DIM * C_DIM * S_DIM];

__device__ __forceinline__ float2 cmul(float2 a, float2 b) {
    return make_float2(a.x * b.x - a.y * b.y, a.x * b.y + a.y * b.x);
}

// ---------------------------------------------------------------------------
// Transpose (B,S,C) -> (B,C,S) into g_scratch
// ---------------------------------------------------------------------------
__global__ void __launch_bounds__(256) transpose_in_kernel(const float* __restrict__ in) {
    __shared__ float tile[32][33];
    const int b = blockIdx.z;
    const int c0 = blockIdx.x * 32;   // channel tile
    const int r0 = blockIdx.y * 32;   // s tile
    const int tx = threadIdx.x, ty = threadIdx.y;
    const float* inb = in + (size_t)b * S_DIM * C_DIM;
    float* outb = g_scratch + (size_t)b * S_DIM * C_DIM;
#pragma unroll
    for (int j = 0; j < 32; j += 8)
        tile[ty + j][tx] = inb[(size_t)(r0 + ty + j) * C_DIM + (c0 + tx)];
    __syncthreads();
#pragma unroll
    for (int j = 0; j < 32; j += 8)
        outb[(size_t)(c0 + ty + j) * S_DIM + (r0 + tx)] = tile[tx][ty + j];
}

// ---------------------------------------------------------------------------
// Transpose g_scratch (B,C,S) -> (B,S,C) into out
// ---------------------------------------------------------------------------
__global__ void __launch_bounds__(256) transpose_out_kernel(float* __restrict__ out) {
    __shared__ float tile[32][33];
    const int b = blockIdx.z;
    const int c0 = blockIdx.x * 32;   // s tile (cols of scratch)
    const int r0 = blockIdx.y * 32;   // channel tile (rows of scratch)
    const int tx = threadIdx.x, ty = threadIdx.y;
    const float* inb = g_scratch + (size_t)b * S_DIM * C_DIM;
    float* outb = out + (size_t)b * S_DIM * C_DIM;
#pragma unroll
    for (int j = 0; j < 32; j += 8)
        tile[ty + j][tx] = inb[(size_t)(r0 + ty + j) * S_DIM + (c0 + tx)];
    __syncthreads();
#pragma unroll
    for (int j = 0; j < 32; j += 8)
        outb[(size_t)(c0 + ty + j) * C_DIM + (r0 + tx)] = tile[tx][ty + j];
}

// ---------------------------------------------------------------------------
// Per-row: rfft(4096) -> top-64 mask -> irfft(4096), in place on g_scratch
//
// Shared layout (floats):
//   A   [2048 float2]  @ 0
//   Bb  [2048 float2]  @ 4096
//   TW  [2048 float2]  @ 8192   TW[t] = (cos(pi t/2048), sin(pi t/2048))
//   X   [2049 float2]  @ 12288
//   M   [2049 float ]  @ 16386
// total = 18435 floats = 73740 bytes
// ---------------------------------------------------------------------------
__global__ void __launch_bounds__(NTHREADS) fft_topk_kernel() {
    extern __shared__ float sh[];
    float2* A  = (float2*)sh;
    float2* Bb = (float2*)(sh + 4096);
    float2* TW = (float2*)(sh + 8192);
    float2* X  = (float2*)(sh + 12288);
    float*  M  = sh + 16386;
    __shared__ int s_cnt;

    const int tid = threadIdx.x;
    float* rowp = g_scratch + (size_t)blockIdx.x * S_DIM;

    // Load packed z[n] = x[2n] + i x[2n+1]
    for (int i = tid; i < N2; i += NTHREADS)
        A[i] = ((const float2*)rowp)[i];
    // Twiddle table: e^{i * 2*pi*t/4096} components
    for (int t = tid; t < N2; t += NTHREADS) {
        float s, c;
        sincospif((float)t * (1.0f / 2048.0f), &s, &c);
        TW[t] = make_float2(c, s);
    }
    __syncthreads();

    // ---- forward complex FFT (2048, Stockham DIF, sign = -1) ----
    float2 *src = A, *dst = Bb;
    int m = 1;
#pragma unroll 1
    for (int st = 0; st < 11; ++st) {
#pragma unroll
        for (int ii = 0; ii < 4; ++ii) {
            int i = tid + ii * NTHREADS;
            int k = i & (m - 1);
            int u = i - k;          // j * m
            float2 a = src[i], b = src[i + 1024];
            float2 w = TW[2 * u]; w.y = -w.y;
            dst[i + u] = make_float2(a.x + b.x, a.y + b.y);
            float2 d = make_float2(a.x - b.x, a.y - b.y);
            dst[i + u + m] = cmul(d, w);
        }
        __syncthreads();
        float2* t = src; src = dst; dst = t;
        m <<= 1;
    }
    float2* Z = src;  // result (Bb after 11 swaps)

    // ---- Hermitian unpack: X[k], k = 0..2048, plus mag^2 ----
    unsigned mv[9];
#pragma unroll
    for (int q = 0; q < 9; ++q) mv[q] = 0u;
#pragma unroll
    for (int q = 0; q < 9; ++q) {
        int k = tid + q * NTHREADS;
        if (k < 2049) {
            int k1 = k & (N2 - 1);
            int k2 = (N2 - k) & (N2 - 1);
            float2 a = Z[k1];
            float2 bc = Z[k2]; bc.y = -bc.y;
            float2 fe = make_float2(0.5f * (a.x + bc.x), 0.5f * (a.y + bc.y));
            float2 d  = make_float2(0.5f * (a.x - bc.x), 0.5f * (a.y - bc.y));
            float2 w  = (k == N2) ? make_float2(-1.0f, 0.0f)
                                  : make_float2(TW[k].x, -TW[k].y);  // e^{-i 2pi k/4096}
            float2 wd = cmul(w, d);
            float2 x = make_float2(fe.x + wd.y, fe.y - wd.x);  // fe - i*(w*d)
            X[k] = x;
            float m2 = x.x * x.x + x.y * x.y;
            M[k] = m2;
            mv[q] = __float_as_uint(m2);
        }
    }
    __syncthreads();

    // ---- binary search for 64th-largest mag^2 (float bits, monotone) ----
    unsigned lo = 0u, hi = 0xffffffffu, thr = 0u;
    bool exact = false;
    while (hi - lo > 1u) {
        unsigned mid = lo + ((hi - lo) >> 1);
        if (tid == 0) s_cnt = 0;
        __syncthreads();
        int v = 0;
#pragma unroll
        for (int q = 0; q < 9; ++q) v += (mv[q] >= mid);
#pragma unroll
        for (int o = 16; o; o >>= 1) v += __shfl_down_sync(0xffffffffu, v, o);
        if ((tid & 31) == 0) atomicAdd(&s_cnt, v);
        __syncthreads();
        int c = s_cnt;
        __syncthreads();
        if (c == TOPK) { thr = mid; exact = true; break; }
        if (c > TOPK) lo = mid; else hi = mid;
    }
    int need = 0;
    if (!exact) {
        thr = lo;  // exact value of the 64th-largest
        if (tid == 0) s_cnt = 0;
        __syncthreads();
        int v = 0;
#pragma unroll
        for (int q = 0; q < 9; ++q) v += (mv[q] > thr);
#pragma unroll
        for (int o = 16; o; o >>= 1) v += __shfl_down_sync(0xffffffffu, v, o);
        if ((tid & 31) == 0) atomicAdd(&s_cnt, v);
        __syncthreads();
        need = TOPK - s_cnt;   // ties at thr to keep, lowest index first
        __syncthreads();
    }

    // ---- zero non-top-k bins ----
#pragma unroll
    for (int q = 0; q < 9; ++q) {
        int k = tid + q * NTHREADS;
        if (k < 2049) {
            unsigned u = mv[q];
            bool keep;
            if (exact) {
                keep = (u >= thr);
            } else if (u > thr) {
                keep = true;
            } else if (u == thr) {
                int r = 0;
                for (int j = 0; j < k; ++j)
                    r += (__float_as_uint(M[j]) == thr);
                keep = (r < need);
            } else {
                keep = false;
            }
            if (!keep) X[k] = make_float2(0.0f, 0.0f);
        }
    }
    __syncthreads();

    // ---- repack filtered spectrum into Z' (write to A) ----
    for (int k = tid; k < N2; k += NTHREADS) {
        float2 xk = X[k];
        float2 xc = X[N2 - k]; xc.y = -xc.y;
        float2 fe = make_float2(0.5f * (xk.x + xc.x), 0.5f * (xk.y + xc.y));
        float2 d  = make_float2(0.5f * (xk.x - xc.x), 0.5f * (xk.y - xc.y));
        float2 fo = cmul(d, TW[k]);             // * e^{+i 2pi k/4096}
        A[k] = make_float2(fe.x - fo.y, fe.y + fo.x);  // fe + i*fo
    }
    __syncthreads();

    // ---- inverse complex FFT (2048, conjugate twiddles) ----
    src = A; dst = Bb; m = 1;
#pragma unroll 1
    for (int st = 0; st < 11; ++st) {
#pragma unroll
        for (int ii = 0; ii < 4; ++ii) {
            int i = tid + ii * NTHREADS;
            int k = i & (m - 1);
            int u = i - k;
            float2 a = src[i], b = src[i + 1024];
            float2 w = TW[2 * u];               // +sin => e^{+i...}
            dst[i + u] = make_float2(a.x + b.x, a.y + b.y);
            float2 d = make_float2(a.x - b.x, a.y - b.y);
            dst[i + u + m] = cmul(d, w);
        }
        __syncthreads();
        float2* t = src; src = dst; dst = t;
        m <<= 1;
    }

    // ---- scale by 1/2048 and store packed samples back ----
    const float sc = 1.0f / 2048.0f;
    for (int i = tid; i < N2; i += NTHREADS) {
        float2 z = src[i];
        ((float2*)rowp)[i] = make_float2(z.x * sc, z.y * sc);
    }
}

// ---------------------------------------------------------------------------
extern "C" void kernel_launch(void* const* d_in, const int* in_sizes, int n_in,
                              void* d_out, int out_size) {
    const float* ts = (const float*)d_in[0];
    float* out = (float*)d_out;

    const int smem_bytes = 73740;
    cudaFuncSetAttribute(fft_topk_kernel,
                         cudaFuncAttributeMaxDynamicSharedMemorySize, smem_bytes);

    dim3 tblk(32, 8);
    // (B,S,C) -> (B,C,S)
    transpose_in_kernel<<<dim3(C_DIM / 32, S_DIM / 32, B_DIM), tblk>>>(ts);
    // per-row FFT + top-k + inverse FFT (in place on scratch)
    fft_topk_kernel<<<B_DIM * C_DIM, NTHREADS, smem_bytes>>>();
    // (B,C,S) -> (B,S,C)
    transpose_out_kernel<<<dim3(S_DIM / 32, C_DIM / 32, B_DIM), tblk>>>(out);
}

// round 4
// speedup vs baseline: 1.5090x; 1.5090x over previous
#include <cuda_runtime.h>
#include <math.h>

// Problem constants
#define B_DIM 64
#define S_DIM 4096
#define C_DIM 128
#define N2 2048          // half-length complex FFT size
#define NT 256
#define TOPK 64

// 128 MB scratch in (B, C, S) layout
__device__ float g_scratch[(size_t)B_DIM * C_DIM * S_DIM];

__device__ __forceinline__ float2 cmul(float2 a, float2 b) {
    return make_float2(a.x * b.x - a.y * b.y, a.x * b.y + a.y * b.x);
}

// Bank swizzle: bijective on [0, 2048); makes all Stockham radix-4
// scatter patterns (stride-4, 16g+r blocks, consecutive) conflict-free.
__device__ __forceinline__ int SW(int i) { return i ^ (i >> 2); }

// ---------------------------------------------------------------------------
// Transpose (B,S,C) -> (B,C,S) into g_scratch
// ---------------------------------------------------------------------------
__global__ void __launch_bounds__(256) transpose_in_kernel(const float* __restrict__ in) {
    __shared__ float tile[32][33];
    const int b = blockIdx.z;
    const int c0 = blockIdx.x * 32;
    const int r0 = blockIdx.y * 32;
    const int tx = threadIdx.x, ty = threadIdx.y;
    const float* inb = in + (size_t)b * S_DIM * C_DIM;
    float* outb = g_scratch + (size_t)b * S_DIM * C_DIM;
#pragma unroll
    for (int j = 0; j < 32; j += 8)
        tile[ty + j][tx] = inb[(size_t)(r0 + ty + j) * C_DIM + (c0 + tx)];
    __syncthreads();
#pragma unroll
    for (int j = 0; j < 32; j += 8)
        outb[(size_t)(c0 + ty + j) * S_DIM + (r0 + tx)] = tile[tx][ty + j];
}

// ---------------------------------------------------------------------------
// Transpose g_scratch (B,C,S) -> (B,S,C) into out
// ---------------------------------------------------------------------------
__global__ void __launch_bounds__(256) transpose_out_kernel(float* __restrict__ out) {
    __shared__ float tile[32][33];
    const int b = blockIdx.z;
    const int c0 = blockIdx.x * 32;
    const int r0 = blockIdx.y * 32;
    const int tx = threadIdx.x, ty = threadIdx.y;
    const float* inb = g_scratch + (size_t)b * S_DIM * C_DIM;
    float* outb = out + (size_t)b * S_DIM * C_DIM;
#pragma unroll
    for (int j = 0; j < 32; j += 8)
        tile[ty + j][tx] = inb[(size_t)(r0 + ty + j) * S_DIM + (c0 + tx)];
    __syncthreads();
#pragma unroll
    for (int j = 0; j < 32; j += 8)
        outb[(size_t)(c0 + ty + j) * C_DIM + (r0 + tx)] = tile[tx][ty + j];
}

// ---------------------------------------------------------------------------
// Radix-4 Stockham stage (generic, smem->smem, swizzled).
// dst[4u + q*L + k] = b_q * W_2048^{+-q*u},  u = i - (i mod L)
// ---------------------------------------------------------------------------
template<int L, bool INV>
__device__ __forceinline__ void r4_stage(const float2* __restrict__ src,
                                         float2* __restrict__ dst,
                                         const float2* __restrict__ TW) {
    const int tid = threadIdx.x;
#pragma unroll
    for (int ii = 0; ii < 2; ++ii) {
        int i = tid + ii * NT;
        int k = i & (L - 1);
        int u = i - k;
        float2 a0 = src[SW(i)];
        float2 a1 = src[SW(i + 512)];
        float2 a2 = src[SW(i + 1024)];
        float2 a3 = src[SW(i + 1536)];
        float2 t0 = make_float2(a0.x + a2.x, a0.y + a2.y);
        float2 t1 = make_float2(a0.x - a2.x, a0.y - a2.y);
        float2 t2 = make_float2(a1.x + a3.x, a1.y + a3.y);
        float2 t3 = make_float2(a1.x - a3.x, a1.y - a3.y);
        float2 b0 = make_float2(t0.x + t2.x, t0.y + t2.y);
        float2 b2 = make_float2(t0.x - t2.x, t0.y - t2.y);
        float2 b1, b3;
        if (!INV) {
            b1 = make_float2(t1.x + t3.y, t1.y - t3.x);   // t1 - i t3
            b3 = make_float2(t1.x - t3.y, t1.y + t3.x);   // t1 + i t3
        } else {
            b1 = make_float2(t1.x - t3.y, t1.y + t3.x);
            b3 = make_float2(t1.x + t3.y, t1.y - t3.x);
        }
        float2 w1 = TW[2 * u];
        if (!INV) w1.y = -w1.y;
        float2 w2 = cmul(w1, w1);
        float2 w3 = cmul(w1, w2);
        int o = 4 * u + k;
        dst[SW(o)]         = b0;
        dst[SW(o + L)]     = cmul(b1, w1);
        dst[SW(o + 2 * L)] = cmul(b2, w2);
        dst[SW(o + 3 * L)] = cmul(b3, w3);
    }
}

// First forward stage (L=1), reading directly from global row.
__device__ __forceinline__ void r4_first_fwd(const float2* __restrict__ g,
                                             float2* __restrict__ dst,
                                             const float2* __restrict__ TW) {
    const int tid = threadIdx.x;
#pragma unroll
    for (int ii = 0; ii < 2; ++ii) {
        int i = tid + ii * NT;
        float2 a0 = g[i];
        float2 a1 = g[i + 512];
        float2 a2 = g[i + 1024];
        float2 a3 = g[i + 1536];
        float2 t0 = make_float2(a0.x + a2.x, a0.y + a2.y);
        float2 t1 = make_float2(a0.x - a2.x, a0.y - a2.y);
        float2 t2 = make_float2(a1.x + a3.x, a1.y + a3.y);
        float2 t3 = make_float2(a1.x - a3.x, a1.y - a3.y);
        float2 b0 = make_float2(t0.x + t2.x, t0.y + t2.y);
        float2 b2 = make_float2(t0.x - t2.x, t0.y - t2.y);
        float2 b1 = make_float2(t1.x + t3.y, t1.y - t3.x);
        float2 b3 = make_float2(t1.x - t3.y, t1.y + t3.x);
        float2 w1 = TW[2 * i]; w1.y = -w1.y;
        float2 w2 = cmul(w1, w1);
        float2 w3 = cmul(w1, w2);
        int o = 4 * i;
        dst[SW(o)]     = b0;
        dst[SW(o + 1)] = cmul(b1, w1);
        dst[SW(o + 2)] = cmul(b2, w2);
        dst[SW(o + 3)] = cmul(b3, w3);
    }
}

// First inverse stage (L=1) fused with Hermitian repack:
// z[k] built on the fly from filtered spectrum X (identity-indexed).
__device__ __forceinline__ void r4_first_inv_repack(const float2* __restrict__ X,
                                                    float2* __restrict__ dst,
                                                    const float2* __restrict__ TW) {
    const int tid = threadIdx.x;
#pragma unroll
    for (int ii = 0; ii < 2; ++ii) {
        int i = tid + ii * NT;
        float2 z[4];
#pragma unroll
        for (int p = 0; p < 4; ++p) {
            int k = i + 512 * p;
            float2 xk = X[k];
            float2 xc = X[2048 - k]; xc.y = -xc.y;
            float2 fe = make_float2(0.5f * (xk.x + xc.x), 0.5f * (xk.y + xc.y));
            float2 d  = make_float2(0.5f * (xk.x - xc.x), 0.5f * (xk.y - xc.y));
            float2 fo = cmul(d, TW[k]);                         // * e^{+i 2pi k/4096}
            z[p] = make_float2(fe.x - fo.y, fe.y + fo.x);       // fe + i*fo
        }
        float2 t0 = make_float2(z[0].x + z[2].x, z[0].y + z[2].y);
        float2 t1 = make_float2(z[0].x - z[2].x, z[0].y - z[2].y);
        float2 t2 = make_float2(z[1].x + z[3].x, z[1].y + z[3].y);
        float2 t3 = make_float2(z[1].x - z[3].x, z[1].y - z[3].y);
        float2 b0 = make_float2(t0.x + t2.x, t0.y + t2.y);
        float2 b2 = make_float2(t0.x - t2.x, t0.y - t2.y);
        float2 b1 = make_float2(t1.x - t3.y, t1.y + t3.x);      // inverse: t1 + i t3
        float2 b3 = make_float2(t1.x + t3.y, t1.y - t3.x);
        float2 w1 = TW[2 * i];                                  // +i twiddles
        float2 w2 = cmul(w1, w1);
        float2 w3 = cmul(w1, w2);
        int o = 4 * i;
        dst[SW(o)]     = b0;
        dst[SW(o + 1)] = cmul(b1, w1);
        dst[SW(o + 2)] = cmul(b2, w2);
        dst[SW(o + 3)] = cmul(b3, w3);
    }
}

// ---------------------------------------------------------------------------
// Per-row: rfft(4096) -> top-64 mask -> irfft(4096), row in g_scratch.
// Shared layout (floats):
//   A  [2048 float2] @ 0      (swizzled ping buffer)
//   Bb [2050 float2] @ 4096   (swizzled pong buffer; X aliases it, identity idx)
//   TW [2048 float2] @ 8196   TW[t] = (cos(pi t/2048), sin(pi t/2048))
//   M  [2049 float ] @ 12292
// total 14341 floats = 57364 bytes
// ---------------------------------------------------------------------------
__global__ void __launch_bounds__(NT) fft_topk_kernel() {
    extern __shared__ float sh[];
    float2* A  = (float2*)sh;
    float2* Bb = (float2*)(sh + 4096);
    float2* TW = (float2*)(sh + 8196);
    float*  M  = sh + 12292;
    float2* X  = Bb;                 // aliases Bb, identity-indexed (2049 entries)
    __shared__ unsigned ws[2][8];

    const int tid = threadIdx.x;
    float* rowp = g_scratch + (size_t)blockIdx.x * S_DIM;
    const float2* gz = (const float2*)rowp;

    // Twiddle table
    for (int t = tid; t < N2; t += NT) {
        float s, c;
        sincospif((float)t * (1.0f / 2048.0f), &s, &c);
        TW[t] = make_float2(c, s);
    }
    __syncthreads();

    // ---- forward FFT: 5 radix-4 stages + twiddle-free radix-2 ----
    r4_first_fwd(gz, Bb, TW);            __syncthreads();
    r4_stage<4,   false>(Bb, A,  TW);    __syncthreads();
    r4_stage<16,  false>(A,  Bb, TW);    __syncthreads();
    r4_stage<64,  false>(Bb, A,  TW);    __syncthreads();
    r4_stage<256, false>(A,  Bb, TW);    __syncthreads();
    // radix-2, L=1024, twiddle-free: Bb -> A  (Z lives in A)
#pragma unroll
    for (int ii = 0; ii < 4; ++ii) {
        int i = tid + ii * NT;
        float2 a = Bb[SW(i)], b = Bb[SW(i + 1024)];
        A[SW(i)]        = make_float2(a.x + b.x, a.y + b.y);
        A[SW(i + 1024)] = make_float2(a.x - b.x, a.y - b.y);
    }
    __syncthreads();

    // ---- Hermitian unpack: X[k] (into Bb, identity idx), mag^2 ----
    unsigned mv[9];
#pragma unroll
    for (int q = 0; q < 9; ++q) mv[q] = 0u;
#pragma unroll
    for (int q = 0; q < 9; ++q) {
        int k = tid + q * NT;
        if (k < 2049) {
            int k1 = k & (N2 - 1);
            int k2 = (N2 - k) & (N2 - 1);
            float2 a  = A[SW(k1)];
            float2 bc = A[SW(k2)]; bc.y = -bc.y;
            float2 fe = make_float2(0.5f * (a.x + bc.x), 0.5f * (a.y + bc.y));
            float2 d  = make_float2(0.5f * (a.x - bc.x), 0.5f * (a.y - bc.y));
            float2 w  = (k == N2) ? make_float2(-1.0f, 0.0f)
                                  : make_float2(TW[k].x, -TW[k].y);
            float2 wd = cmul(w, d);
            float2 x = make_float2(fe.x + wd.y, fe.y - wd.x);  // fe - i*(w*d)
            X[k] = x;
            float m2 = x.x * x.x + x.y * x.y;
            M[k] = m2;
            mv[q] = __float_as_uint(m2);
        }
    }
    __syncthreads();

    // ---- block max seed for the search ----
    {
        unsigned vm = 0;
#pragma unroll
        for (int q = 0; q < 9; ++q) vm = max(vm, mv[q]);
        vm = __reduce_max_sync(0xffffffffu, vm);
        if ((tid & 31) == 0) ws[1][tid >> 5] = vm;
    }
    __syncthreads();
    unsigned mx = 0;
#pragma unroll
    for (int w = 0; w < 8; ++w) mx = max(mx, ws[1][w]);

    // ---- binary search for the 64th-largest mag^2 (1 barrier / iter) ----
    unsigned lo = 0u, hi = mx + 1u, thr = 0u;
    bool exact = false;
    int it = 0;
    while (hi - lo > 1u) {
        unsigned mid = lo + ((hi - lo) >> 1);
        unsigned v = 0;
#pragma unroll
        for (int q = 0; q < 9; ++q) v += (mv[q] >= mid);
        v = __reduce_add_sync(0xffffffffu, v);
        if ((tid & 31) == 0) ws[it & 1][tid >> 5] = v;
        __syncthreads();
        unsigned c = 0;
#pragma unroll
        for (int w = 0; w < 8; ++w) c += ws[it & 1][w];
        if (c == TOPK) { thr = mid; exact = true; break; }
        if (c > TOPK) lo = mid; else hi = mid;
        ++it;
    }
    int need = 0;
    if (!exact) {
        thr = lo;
        unsigned v = 0;
#pragma unroll
        for (int q = 0; q < 9; ++q) v += (mv[q] > thr);
        v = __reduce_add_sync(0xffffffffu, v);
        if ((tid & 31) == 0) ws[(it + 1) & 1][tid >> 5] = v;
        __syncthreads();
        unsigned c = 0;
#pragma unroll
        for (int w = 0; w < 8; ++w) c += ws[(it + 1) & 1][w];
        need = TOPK - (int)c;   // ties at thr kept lowest-index-first
    }

    // ---- zero non-top-k bins ----
#pragma unroll
    for (int q = 0; q < 9; ++q) {
        int k = tid + q * NT;
        if (k < 2049) {
            unsigned u = mv[q];
            bool keep;
            if (exact) {
                keep = (u >= thr);
            } else if (u > thr) {
                keep = true;
            } else if (u == thr) {
                int r = 0;
                for (int j = 0; j < k; ++j)
                    r += (__float_as_uint(M[j]) == thr);
                keep = (r < need);
            } else {
                keep = false;
            }
            if (!keep) X[k] = make_float2(0.0f, 0.0f);
        }
    }
    __syncthreads();

    // ---- inverse FFT: repack fused into first radix-4 stage ----
    r4_first_inv_repack(X, A, TW);       __syncthreads();
    r4_stage<4,   true>(A,  Bb, TW);     __syncthreads();
    r4_stage<16,  true>(Bb, A,  TW);     __syncthreads();
    r4_stage<64,  true>(A,  Bb, TW);     __syncthreads();
    r4_stage<256, true>(Bb, A,  TW);     __syncthreads();
    // radix-2, L=1024, twiddle-free, scaled, write straight to global
    const float sc = 1.0f / 2048.0f;
    float2* go = (float2*)rowp;
#pragma unroll
    for (int ii = 0; ii < 4; ++ii) {
        int i = tid + ii * NT;
        float2 a = A[SW(i)], b = A[SW(i + 1024)];
        go[i]        = make_float2((a.x + b.x) * sc, (a.y + b.y) * sc);
        go[i + 1024] = make_float2((a.x - b.x) * sc, (a.y - b.y) * sc);
    }
}

// ---------------------------------------------------------------------------
extern "C" void kernel_launch(void* const* d_in, const int* in_sizes, int n_in,
                              void* d_out, int out_size) {
    const float* ts = (const float*)d_in[0];
    float* out = (float*)d_out;

    const int smem_bytes = 57364;
    cudaFuncSetAttribute(fft_topk_kernel,
                         cudaFuncAttributeMaxDynamicSharedMemorySize, smem_bytes);

    dim3 tblk(32, 8);
    transpose_in_kernel<<<dim3(C_DIM / 32, S_DIM / 32, B_DIM), tblk>>>(ts);
    fft_topk_kernel<<<B_DIM * C_DIM, NT, smem_bytes>>>();
    transpose_out_kernel<<<dim3(S_DIM / 32, C_DIM / 32, B_DIM), tblk>>>(out);
}

// round 5
// speedup vs baseline: 1.6070x; 1.0649x over previous
#include <cuda_runtime.h>
#include <math.h>

// Problem constants
#define B_DIM 64
#define S_DIM 4096
#define C_DIM 128
#define N2 2048          // half-length complex FFT size
#define NT 256
#define TOPK 64

// 128 MB scratch in (B, C, S) layout
__device__ float g_scratch[(size_t)B_DIM * C_DIM * S_DIM];
// Twiddle table in global: g_tw[t] = (cos(pi t/2048), sin(pi t/2048))
__device__ float2 g_tw[N2];

__device__ __forceinline__ float2 cmul(float2 a, float2 b) {
    return make_float2(a.x * b.x - a.y * b.y, a.x * b.y + a.y * b.x);
}

// Bank swizzle: bijective on [0, 2048); makes all Stockham radix-4
// scatter patterns (stride-4, 16g+r blocks, consecutive) conflict-free.
__device__ __forceinline__ int SW(int i) { return i ^ (i >> 2); }

// Bit-exact mag^2 (used for both the ranking values and the tie re-check).
__device__ __forceinline__ unsigned mag2u(float2 x) {
    return __float_as_uint(__fadd_rn(__fmul_rn(x.x, x.x), __fmul_rn(x.y, x.y)));
}

// ---------------------------------------------------------------------------
__global__ void __launch_bounds__(256) init_tw_kernel() {
    int t = blockIdx.x * 256 + threadIdx.x;
    float s, c;
    sincospif((float)t * (1.0f / 2048.0f), &s, &c);
    g_tw[t] = make_float2(c, s);
}

// ---------------------------------------------------------------------------
// Transpose (B,S,C) -> (B,C,S) into g_scratch
// ---------------------------------------------------------------------------
__global__ void __launch_bounds__(256) transpose_in_kernel(const float* __restrict__ in) {
    __shared__ float tile[32][33];
    const int b = blockIdx.z;
    const int c0 = blockIdx.x * 32;
    const int r0 = blockIdx.y * 32;
    const int tx = threadIdx.x, ty = threadIdx.y;
    const float* inb = in + (size_t)b * S_DIM * C_DIM;
    float* outb = g_scratch + (size_t)b * S_DIM * C_DIM;
#pragma unroll
    for (int j = 0; j < 32; j += 8)
        tile[ty + j][tx] = inb[(size_t)(r0 + ty + j) * C_DIM + (c0 + tx)];
    __syncthreads();
#pragma unroll
    for (int j = 0; j < 32; j += 8)
        outb[(size_t)(c0 + ty + j) * S_DIM + (r0 + tx)] = tile[tx][ty + j];
}

// ---------------------------------------------------------------------------
// Transpose g_scratch (B,C,S) -> (B,S,C) into out
// ---------------------------------------------------------------------------
__global__ void __launch_bounds__(256) transpose_out_kernel(float* __restrict__ out) {
    __shared__ float tile[32][33];
    const int b = blockIdx.z;
    const int c0 = blockIdx.x * 32;
    const int r0 = blockIdx.y * 32;
    const int tx = threadIdx.x, ty = threadIdx.y;
    const float* inb = g_scratch + (size_t)b * S_DIM * C_DIM;
    float* outb = out + (size_t)b * S_DIM * C_DIM;
#pragma unroll
    for (int j = 0; j < 32; j += 8)
        tile[ty + j][tx] = inb[(size_t)(r0 + ty + j) * S_DIM + (c0 + tx)];
    __syncthreads();
#pragma unroll
    for (int j = 0; j < 32; j += 8)
        outb[(size_t)(c0 + ty + j) * C_DIM + (r0 + tx)] = tile[tx][ty + j];
}

// ---------------------------------------------------------------------------
// Radix-4 Stockham stage (generic, smem->smem, swizzled). Twiddles from global.
// ---------------------------------------------------------------------------
template<int L, bool INV>
__device__ __forceinline__ void r4_stage(const float2* __restrict__ src,
                                         float2* __restrict__ dst,
                                         const float2* __restrict__ TW) {
    const int tid = threadIdx.x;
#pragma unroll
    for (int ii = 0; ii < 2; ++ii) {
        int i = tid + ii * NT;
        int k = i & (L - 1);
        int u = i - k;
        float2 a0 = src[SW(i)];
        float2 a1 = src[SW(i + 512)];
        float2 a2 = src[SW(i + 1024)];
        float2 a3 = src[SW(i + 1536)];
        float2 t0 = make_float2(a0.x + a2.x, a0.y + a2.y);
        float2 t1 = make_float2(a0.x - a2.x, a0.y - a2.y);
        float2 t2 = make_float2(a1.x + a3.x, a1.y + a3.y);
        float2 t3 = make_float2(a1.x - a3.x, a1.y - a3.y);
        float2 b0 = make_float2(t0.x + t2.x, t0.y + t2.y);
        float2 b2 = make_float2(t0.x - t2.x, t0.y - t2.y);
        float2 b1, b3;
        if (!INV) {
            b1 = make_float2(t1.x + t3.y, t1.y - t3.x);   // t1 - i t3
            b3 = make_float2(t1.x - t3.y, t1.y + t3.x);   // t1 + i t3
        } else {
            b1 = make_float2(t1.x - t3.y, t1.y + t3.x);
            b3 = make_float2(t1.x + t3.y, t1.y - t3.x);
        }
        float2 w1 = TW[2 * u];
        if (!INV) w1.y = -w1.y;
        float2 w2 = cmul(w1, w1);
        float2 w3 = cmul(w1, w2);
        int o = 4 * u + k;
        dst[SW(o)]         = b0;
        dst[SW(o + L)]     = cmul(b1, w1);
        dst[SW(o + 2 * L)] = cmul(b2, w2);
        dst[SW(o + 3 * L)] = cmul(b3, w3);
    }
}

// First forward stage (L=1), reading directly from global row.
__device__ __forceinline__ void r4_first_fwd(const float2* __restrict__ g,
                                             float2* __restrict__ dst,
                                             const float2* __restrict__ TW) {
    const int tid = threadIdx.x;
#pragma unroll
    for (int ii = 0; ii < 2; ++ii) {
        int i = tid + ii * NT;
        float2 a0 = g[i];
        float2 a1 = g[i + 512];
        float2 a2 = g[i + 1024];
        float2 a3 = g[i + 1536];
        float2 t0 = make_float2(a0.x + a2.x, a0.y + a2.y);
        float2 t1 = make_float2(a0.x - a2.x, a0.y - a2.y);
        float2 t2 = make_float2(a1.x + a3.x, a1.y + a3.y);
        float2 t3 = make_float2(a1.x - a3.x, a1.y - a3.y);
        float2 b0 = make_float2(t0.x + t2.x, t0.y + t2.y);
        float2 b2 = make_float2(t0.x - t2.x, t0.y - t2.y);
        float2 b1 = make_float2(t1.x + t3.y, t1.y - t3.x);
        float2 b3 = make_float2(t1.x - t3.y, t1.y + t3.x);
        float2 w1 = TW[2 * i]; w1.y = -w1.y;
        float2 w2 = cmul(w1, w1);
        float2 w3 = cmul(w1, w2);
        int o = 4 * i;
        dst[SW(o)]     = b0;
        dst[SW(o + 1)] = cmul(b1, w1);
        dst[SW(o + 2)] = cmul(b2, w2);
        dst[SW(o + 3)] = cmul(b3, w3);
    }
}

// First inverse stage (L=1) fused with Hermitian repack.
__device__ __forceinline__ void r4_first_inv_repack(const float2* __restrict__ X,
                                                    float2* __restrict__ dst,
                                                    const float2* __restrict__ TW) {
    const int tid = threadIdx.x;
#pragma unroll
    for (int ii = 0; ii < 2; ++ii) {
        int i = tid + ii * NT;
        float2 z[4];
#pragma unroll
        for (int p = 0; p < 4; ++p) {
            int k = i + 512 * p;
            float2 xk = X[k];
            float2 xc = X[2048 - k]; xc.y = -xc.y;
            float2 fe = make_float2(0.5f * (xk.x + xc.x), 0.5f * (xk.y + xc.y));
            float2 d  = make_float2(0.5f * (xk.x - xc.x), 0.5f * (xk.y - xc.y));
            float2 fo = cmul(d, TW[k]);                         // * e^{+i 2pi k/4096}
            z[p] = make_float2(fe.x - fo.y, fe.y + fo.x);       // fe + i*fo
        }
        float2 t0 = make_float2(z[0].x + z[2].x, z[0].y + z[2].y);
        float2 t1 = make_float2(z[0].x - z[2].x, z[0].y - z[2].y);
        float2 t2 = make_float2(z[1].x + z[3].x, z[1].y + z[3].y);
        float2 t3 = make_float2(z[1].x - z[3].x, z[1].y - z[3].y);
        float2 b0 = make_float2(t0.x + t2.x, t0.y + t2.y);
        float2 b2 = make_float2(t0.x - t2.x, t0.y - t2.y);
        float2 b1 = make_float2(t1.x - t3.y, t1.y + t3.x);      // inverse: t1 + i t3
        float2 b3 = make_float2(t1.x + t3.y, t1.y - t3.x);
        float2 w1 = TW[2 * i];                                  // +i twiddles
        float2 w2 = cmul(w1, w1);
        float2 w3 = cmul(w1, w2);
        int o = 4 * i;
        dst[SW(o)]     = b0;
        dst[SW(o + 1)] = cmul(b1, w1);
        dst[SW(o + 2)] = cmul(b2, w2);
        dst[SW(o + 3)] = cmul(b3, w3);
    }
}

// ---------------------------------------------------------------------------
// Per-row: rfft(4096) -> top-64 mask -> irfft(4096), row in g_scratch.
// Shared layout (floats):
//   A  [2048 float2] @ 0      (swizzled ping buffer)
//   Bb [2052 float2] @ 4096   (swizzled pong buffer; X aliases it, identity idx)
// total 8200 floats = 32800 bytes
// ---------------------------------------------------------------------------
__global__ void __launch_bounds__(NT, 6) fft_topk_kernel() {
    extern __shared__ float sh[];
    float2* A  = (float2*)sh;
    float2* Bb = (float2*)(sh + 4096);
    float2* X  = Bb;                 // aliases Bb, identity-indexed (2049 entries)
    const float2* TW = g_tw;
    __shared__ unsigned ws[2][8];

    const int tid = threadIdx.x;
    float* rowp = g_scratch + (size_t)blockIdx.x * S_DIM;
    const float2* gz = (const float2*)rowp;

    // ---- forward FFT: 5 radix-4 stages + twiddle-free radix-2 ----
    r4_first_fwd(gz, Bb, TW);            __syncthreads();
    r4_stage<4,   false>(Bb, A,  TW);    __syncthreads();
    r4_stage<16,  false>(A,  Bb, TW);    __syncthreads();
    r4_stage<64,  false>(Bb, A,  TW);    __syncthreads();
    r4_stage<256, false>(A,  Bb, TW);    __syncthreads();
    // radix-2, L=1024, twiddle-free: Bb -> A  (Z lives in A)
#pragma unroll
    for (int ii = 0; ii < 4; ++ii) {
        int i = tid + ii * NT;
        float2 a = Bb[SW(i)], b = Bb[SW(i + 1024)];
        A[SW(i)]        = make_float2(a.x + b.x, a.y + b.y);
        A[SW(i + 1024)] = make_float2(a.x - b.x, a.y - b.y);
    }
    __syncthreads();

    // ---- Hermitian unpack: X[k] (into Bb, identity idx), mag^2 bits ----
    unsigned mv[9];
#pragma unroll
    for (int q = 0; q < 9; ++q) mv[q] = 0u;
#pragma unroll
    for (int q = 0; q < 9; ++q) {
        int k = tid + q * NT;
        if (k < 2049) {
            int k1 = k & (N2 - 1);
            int k2 = (N2 - k) & (N2 - 1);
            float2 a  = A[SW(k1)];
            float2 bc = A[SW(k2)]; bc.y = -bc.y;
            float2 fe = make_float2(0.5f * (a.x + bc.x), 0.5f * (a.y + bc.y));
            float2 d  = make_float2(0.5f * (a.x - bc.x), 0.5f * (a.y - bc.y));
            float2 w  = (k == N2) ? make_float2(-1.0f, 0.0f)
                                  : make_float2(TW[k].x, -TW[k].y);
            float2 wd = cmul(w, d);
            float2 x = make_float2(fe.x + wd.y, fe.y - wd.x);  // fe - i*(w*d)
            X[k] = x;
            mv[q] = mag2u(x);
        }
    }
    __syncthreads();

    // ---- block max seed for the search ----
    {
        unsigned vm = 0;
#pragma unroll
        for (int q = 0; q < 9; ++q) vm = max(vm, mv[q]);
        vm = __reduce_max_sync(0xffffffffu, vm);
        if ((tid & 31) == 0) ws[1][tid >> 5] = vm;
    }
    __syncthreads();
    unsigned mx = 0;
#pragma unroll
    for (int w = 0; w < 8; ++w) mx = max(mx, ws[1][w]);

    // ---- binary search for the 64th-largest mag^2 (1 barrier / iter) ----
    unsigned lo = 0u, hi = mx + 1u, thr = 0u;
    bool exact = false;
    int it = 0;
    while (hi - lo > 1u) {
        unsigned mid = lo + ((hi - lo) >> 1);
        unsigned v = 0;
#pragma unroll
        for (int q = 0; q < 9; ++q) v += (mv[q] >= mid);
        v = __reduce_add_sync(0xffffffffu, v);
        if ((tid & 31) == 0) ws[it & 1][tid >> 5] = v;
        __syncthreads();
        unsigned c = 0;
#pragma unroll
        for (int w = 0; w < 8; ++w) c += ws[it & 1][w];
        if (c == TOPK) { thr = mid; exact = true; break; }
        if (c > TOPK) lo = mid; else hi = mid;
        ++it;
    }
    int need = 0;
    if (!exact) {
        thr = lo;
        unsigned v = 0;
#pragma unroll
        for (int q = 0; q < 9; ++q) v += (mv[q] > thr);
        v = __reduce_add_sync(0xffffffffu, v);
        if ((tid & 31) == 0) ws[(it + 1) & 1][tid >> 5] = v;
        __syncthreads();
        unsigned c = 0;
#pragma unroll
        for (int w = 0; w < 8; ++w) c += ws[(it + 1) & 1][w];
        need = TOPK - (int)c;   // ties at thr kept lowest-index-first
    }

    // ---- keep decisions first (X stable), then barrier, then zero ----
    unsigned keepmask = 0u;
#pragma unroll
    for (int q = 0; q < 9; ++q) {
        int k = tid + q * NT;
        if (k < 2049) {
            unsigned u = mv[q];
            bool keep;
            if (exact) {
                keep = (u >= thr);
            } else if (u > thr) {
                keep = true;
            } else if (u == thr) {
                int r = 0;
                for (int j = 0; j < k; ++j)
                    r += (mag2u(X[j]) == thr);
                keep = (r < need);
            } else {
                keep = false;
            }
            if (keep) keepmask |= (1u << q);
        }
    }
    __syncthreads();
#pragma unroll
    for (int q = 0; q < 9; ++q) {
        int k = tid + q * NT;
        if (k < 2049 && !(keepmask & (1u << q)))
            X[k] = make_float2(0.0f, 0.0f);
    }
    __syncthreads();

    // ---- inverse FFT: repack fused into first radix-4 stage ----
    r4_first_inv_repack(X, A, TW);       __syncthreads();
    r4_stage<4,   true>(A,  Bb, TW);     __syncthreads();
    r4_stage<16,  true>(Bb, A,  TW);     __syncthreads();
    r4_stage<64,  true>(A,  Bb, TW);     __syncthreads();
    r4_stage<256, true>(Bb, A,  TW);     __syncthreads();
    // radix-2, L=1024, twiddle-free, scaled, write straight to global
    const float sc = 1.0f / 2048.0f;
    float2* go = (float2*)rowp;
#pragma unroll
    for (int ii = 0; ii < 4; ++ii) {
        int i = tid + ii * NT;
        float2 a = A[SW(i)], b = A[SW(i + 1024)];
        go[i]        = make_float2((a.x + b.x) * sc, (a.y + b.y) * sc);
        go[i + 1024] = make_float2((a.x - b.x) * sc, (a.y - b.y) * sc);
    }
}

// ---------------------------------------------------------------------------
extern "C" void kernel_launch(void* const* d_in, const int* in_sizes, int n_in,
                              void* d_out, int out_size) {
    const float* ts = (const float*)d_in[0];
    float* out = (float*)d_out;

    const int smem_bytes = 32800;
    cudaFuncSetAttribute(fft_topk_kernel,
                         cudaFuncAttributeMaxDynamicSharedMemorySize, smem_bytes);

    dim3 tblk(32, 8);
    init_tw_kernel<<<N2 / 256, 256>>>();
    transpose_in_kernel<<<dim3(C_DIM / 32, S_DIM / 32, B_DIM), tblk>>>(ts);
    fft_topk_kernel<<<B_DIM * C_DIM, NT, smem_bytes>>>();
    transpose_out_kernel<<<dim3(S_DIM / 32, C_DIM / 32, B_DIM), tblk>>>(out);
}